// round 16
// baseline (speedup 1.0000x reference)
#include <cuda_runtime.h>
#include <math.h>

// Problem shape (fixed by the dataset)
#define W_ 160
#define H_ 128
#define C_ 32
#define G_ 8
#define D_ 48
#define S_ 2
#define HW_ (H_ * W_)
#define DBLK_ 8
#define NDB_ (D_ / DBLK_)

#define SNAP_ 3e-5f
#define LOG2E_ 1.44269504088896340736f

typedef unsigned long long u64;

// Scratch (no cudaMalloc allowed)
__device__ float4 g_ref4[G_ * HW_];          // ref softmax, channel-packed
__device__ float4 g_src4[S_ * G_ * HW_];     // src features, channel-packed
__device__ float g_rot[S_][9];
__device__ float g_trans[S_][3];
__device__ float g_w1[G_];
__device__ float g_aff[4];  // s1, c1, w2, b2
// Fast-geometry tables (valid when g_fast != 0): per (s, depth-block) base
// integer shift and per (s,d) 3-slot aligned bilinear weights (log2e folded).
__device__ int    g_fast;
__device__ int    g_kb[S_][NDB_];
__device__ float4 g_w3[S_][D_];

__device__ __forceinline__ float ex2f(float x) {
    float y; asm("ex2.approx.f32 %0, %1;" : "=f"(y) : "f"(x)); return y;
}
__device__ __forceinline__ u64 pk2(float a, float b) {
    u64 r; asm("mov.b64 %0, {%1, %2};" : "=l"(r) : "f"(a), "f"(b)); return r;
}
__device__ __forceinline__ void upk2(u64 v, float& a, float& b) {
    asm("mov.b64 {%0, %1}, %2;" : "=f"(a), "=f"(b) : "l"(v));
}
__device__ __forceinline__ u64 fma2(u64 a, u64 b, u64 c) {
    u64 r; asm("fma.rn.f32x2 %0, %1, %2, %3;" : "=l"(r) : "l"(a), "l"(b), "l"(c)); return r;
}
__device__ __forceinline__ u64 mul2(u64 a, u64 b) {
    u64 r; asm("mul.rn.f32x2 %0, %1, %2;" : "=l"(r) : "l"(a), "l"(b)); return r;
}

// ---------------------------------------------------------------------------
// Prep (same structure as R12/R15; DBLK-dependent tables adapt via macros)
// ---------------------------------------------------------------------------
#define T1_ (S_ * G_ * HW_)
#define T2_ (T1_ + G_ * HW_)

__global__ __launch_bounds__(256) void prep_all_kernel(
    const float* __restrict__ ref_feature,
    const float* __restrict__ srcF,
    const float* __restrict__ ref_proj,
    const float* __restrict__ src_projs,
    const float* __restrict__ depths,
    const float* __restrict__ w1,
    const float* __restrict__ bn_gamma,
    const float* __restrict__ bn_beta,
    const float* __restrict__ bn_mean,
    const float* __restrict__ bn_var,
    const float* __restrict__ w2,
    const float* __restrict__ b2) {
    int t = blockIdx.x * blockDim.x + threadIdx.x;

    if (blockIdx.x == 0) {
        if (threadIdx.x == 0) {
            float a[4][8];
            for (int i = 0; i < 4; i++)
                for (int j = 0; j < 4; j++) {
                    a[i][j] = ref_proj[i * 4 + j];
                    a[i][4 + j] = (i == j) ? 1.0f : 0.0f;
                }
            for (int col = 0; col < 4; col++) {
                int piv = col;
                float best = fabsf(a[col][col]);
                for (int r = col + 1; r < 4; r++) {
                    float v = fabsf(a[r][col]);
                    if (v > best) { best = v; piv = r; }
                }
                if (piv != col)
                    for (int j = 0; j < 8; j++) {
                        float tmp = a[col][j]; a[col][j] = a[piv][j]; a[piv][j] = tmp;
                    }
                float inv = 1.0f / a[col][col];
                for (int j = 0; j < 8; j++) a[col][j] *= inv;
                for (int r = 0; r < 4; r++) {
                    if (r == col) continue;
                    float f = a[r][col];
                    for (int j = 0; j < 8; j++) a[r][j] -= f * a[col][j];
                }
            }
            for (int s = 0; s < S_; s++) {
                const float* sp = src_projs + s * 16;
                for (int i = 0; i < 3; i++) {
                    float pr[4];
                    for (int j = 0; j < 4; j++) {
                        float acc = 0.0f;
                        for (int k = 0; k < 4; k++)
                            acc += sp[i * 4 + k] * a[k][4 + j];
                        pr[j] = acc;
                    }
                    g_rot[s][i * 3 + 0] = pr[0];
                    g_rot[s][i * 3 + 1] = pr[1];
                    g_rot[s][i * 3 + 2] = pr[2];
                    g_trans[s][i] = pr[3];
                }
            }
            for (int g = 0; g < G_; g++) g_w1[g] = w1[g];
            float s1 = bn_gamma[0] * rsqrtf(bn_var[0] + 1e-5f);
            float c1 = bn_beta[0] - bn_mean[0] * s1;
            g_aff[0] = s1;
            g_aff[1] = c1;
            g_aff[2] = w2[0];
            g_aff[3] = b2[0];

            bool fast = true;
            for (int s = 0; s < S_; s++) {
                for (int i = 0; i < 3; i++)
                    for (int j = 0; j < 3; j++) {
                        float expect = (i == j) ? 1.0f : 0.0f;
                        if (fabsf(g_rot[s][i * 3 + j] - expect) > 1e-3f) fast = false;
                    }
                if (fabsf(g_trans[s][1]) > 1e-3f) fast = false;
                if (fabsf(g_trans[s][2]) > 1e-3f) fast = false;
            }
            g_fast = fast ? 1 : 0;
        }
        __syncthreads();  // block-uniform
        if (threadIdx.x < S_ * D_) {
            int s = threadIdx.x / D_;
            int d = threadIdx.x % D_;
            int dblk = d / DBLK_;
            float t0 = g_trans[s][0];
            int kmin = 0x7fffffff, kd = 0;
            float wxd = 0.0f;
            for (int dl = 0; dl < DBLK_; dl++) {
                int dd = dblk * DBLK_ + dl;
                float shift = __fdividef(t0, depths[dd]);
                float fs = floorf(shift);
                float wx = shift - fs;
                if (wx < SNAP_) { wx = 0.0f; }
                else if (wx > 1.0f - SNAP_) { wx = 0.0f; fs += 1.0f; }
                int k = (int)fs;
                kmin = min(kmin, k);
                if (dd == d) { kd = k; wxd = wx; }
            }
            if ((d % DBLK_) == 0) g_kb[s][dblk] = kmin;
            int delta = kd - kmin;
            if (delta > 1) atomicExch(&g_fast, 0);  // fast tables invalid
            float wlo = (1.0f - wxd) * LOG2E_;
            float whi = wxd * LOG2E_;
            float4 w3 = make_float4(0.0f, 0.0f, 0.0f, 0.0f);
            if (delta == 0) { w3.x = wlo; w3.y = whi; }
            else            { w3.y = wlo; w3.z = whi; }
            g_w3[s][d] = w3;
        }
    }

    if (t < T1_) {
        int p = t % HW_;
        int sg = t / HW_;
        int s = sg / G_;
        int g = sg % G_;
        const float* b = srcF + (s * C_ + 4 * g) * HW_ + p;
        float4 v;
        v.x = b[0];
        v.y = b[HW_];
        v.z = b[2 * HW_];
        v.w = b[3 * HW_];
        g_src4[sg * HW_ + p] = v;
    } else if (t < T2_) {
        int u = t - T1_;
        int p = u % HW_;
        int g = u / HW_;
        const float* b = ref_feature + (g * 4) * HW_ + p;
        float e0 = __expf(b[0]);
        float e1 = __expf(b[HW_]);
        float e2 = __expf(b[2 * HW_]);
        float e3 = __expf(b[3 * HW_]);
        float is = __fdividef(1.0f, (e0 + e1) + (e2 + e3));
        float4 o;
        o.x = e0 * is;
        o.y = e1 * is;
        o.z = e2 * is;
        o.w = e3 * is;
        g_ref4[g * HW_ + p] = o;
    }
}

// ---------------------------------------------------------------------------
// General-geometry fallback, quarantined (never executed on degenerate
// projections; keeps fat geometry out of the fast path's register budget).
// ---------------------------------------------------------------------------
__device__ __noinline__ void general_body(int x, int y, int p, int g, int d0,
                                          const float* __restrict__ depths,
                                          float* v0, float* v1) {
    const float4* sb0 = g_src4 + (0 * G_ + g) * HW_;
    const float4* sb1 = g_src4 + (1 * G_ + g) * HW_;
    float4 r = g_ref4[g * HW_ + p];
    float xf = (float)x, yf = (float)y;
    for (int dl = 0; dl < DBLK_; dl++) {
        float depth = __ldg(depths + d0 + dl);
        float vv[2];
        for (int s = 0; s < S_; s++) {
            float X = fmaf(fmaf(g_rot[s][0], xf, fmaf(g_rot[s][1], yf, g_rot[s][2])), depth, g_trans[s][0]);
            float Y = fmaf(fmaf(g_rot[s][3], xf, fmaf(g_rot[s][4], yf, g_rot[s][5])), depth, g_trans[s][1]);
            float Z = fmaf(fmaf(g_rot[s][6], xf, fmaf(g_rot[s][7], yf, g_rot[s][8])), depth, g_trans[s][2]);
            float iz = __fdividef(1.0f, Z);
            float px = X * iz;
            float py = Y * iz;
            float x0f = floorf(px), y0f = floorf(py);
            float wx = px - x0f, wy = py - y0f;
            if (wx < SNAP_) { wx = 0.0f; }
            else if (wx > 1.0f - SNAP_) { wx = 0.0f; x0f += 1.0f; }
            if (wy < SNAP_) { wy = 0.0f; }
            else if (wy > 1.0f - SNAP_) { wy = 0.0f; y0f += 1.0f; }
            float vx0 = (x0f >= 0.0f && x0f <= (float)(W_ - 1)) ? LOG2E_ : 0.0f;
            float vx1 = (x0f + 1.0f >= 0.0f && x0f + 1.0f <= (float)(W_ - 1)) ? LOG2E_ : 0.0f;
            float vy0 = (y0f >= 0.0f && y0f <= (float)(H_ - 1)) ? 1.0f : 0.0f;
            float vy1 = (y0f + 1.0f >= 0.0f && y0f + 1.0f <= (float)(H_ - 1)) ? 1.0f : 0.0f;
            float wl = (1.0f - wx) * vx0, wr = wx * vx1;
            float wt = (1.0f - wy) * vy0, wb = wy * vy1;
            int xi0 = min(max((int)x0f, 0), W_ - 1);
            int yi0 = min(max((int)y0f, 0), H_ - 1);
            int xi1 = min(max((int)x0f + 1, 0), W_ - 1);
            int yi1 = min(max((int)y0f + 1, 0), H_ - 1);
            const float4* sb = (s == 0) ? sb0 : sb1;
            float4 qa = sb[yi0 * W_ + xi0];
            float4 qb = sb[yi0 * W_ + xi1];
            float4 qc = sb[yi1 * W_ + xi0];
            float4 qd = sb[yi1 * W_ + xi1];
            float w00 = wl * wt, w01 = wr * wt, w10 = wl * wb, w11 = wr * wb;
            float a0 = fmaf(w00, qa.x, fmaf(w01, qb.x, fmaf(w10, qc.x, w11 * qd.x)));
            float a1 = fmaf(w00, qa.y, fmaf(w01, qb.y, fmaf(w10, qc.y, w11 * qd.y)));
            float a2 = fmaf(w00, qa.z, fmaf(w01, qb.z, fmaf(w10, qc.z, w11 * qd.z)));
            float a3 = fmaf(w00, qa.w, fmaf(w01, qb.w, fmaf(w10, qc.w, w11 * qd.w)));
            float e0 = ex2f(a0), e1 = ex2f(a1);
            float e2 = ex2f(a2), e3 = ex2f(a3);
            float ss = (e0 + e1) + (e2 + e3);
            float num = fmaf(e0, r.x, fmaf(e1, r.y, fmaf(e2, r.z, e3 * r.w)));
            vv[s] = __fdividef(num, ss);
        }
        v0[dl] = vv[0];
        v1[dl] = vv[1];
    }
}

// Depth loop over pre-loaded taps (float4 weights + pk2 dup, proven in R12).
__device__ __forceinline__ void depth_loop(const ulonglong2* q, int s, int d0,
                                           float4 r, float* vs) {
#pragma unroll
    for (int dl = 0; dl < DBLK_; dl++) {
        float4 w3 = g_w3[s][d0 + dl];
        u64 wa = pk2(w3.x, w3.x);
        u64 wb = pk2(w3.y, w3.y);
        u64 wc = pk2(w3.z, w3.z);
        u64 a01 = fma2(wa, q[0].x, fma2(wb, q[1].x, mul2(wc, q[2].x)));
        u64 a23 = fma2(wa, q[0].y, fma2(wb, q[1].y, mul2(wc, q[2].y)));
        float a0, a1, a2, a3;
        upk2(a01, a0, a1);
        upk2(a23, a2, a3);
        float e0 = ex2f(a0), e1 = ex2f(a1);
        float e2 = ex2f(a2), e3 = ex2f(a3);
        float ss = (e0 + e1) + (e2 + e3);
        float num = fmaf(e0, r.x, fmaf(e1, r.y, fmaf(e2, r.z, e3 * r.w)));
        vs[dl] = __fdividef(num, ss);
    }
}

// ---------------------------------------------------------------------------
// Main fused kernel. Grid (W/32, H, D/8); block (32, 8).
// Thread = (x, y, group g, 8 consecutive depths): 3 taps/source loaded once
// serve 8 depths. All 8 warps act as reducers in the epilogue (dl = g).
// ---------------------------------------------------------------------------
__global__ __launch_bounds__(256, 3) void fuse_kernel(const float* __restrict__ depths,
                                                      float* __restrict__ out) {
    __shared__ float s_lin[DBLK_][2][G_][32];  // [dl][src][g][tx]
    __shared__ float s_w[DBLK_][2][32];        // [dl][src][tx] = wgt*iw

    int tx = threadIdx.x;
    int g = threadIdx.y;                  // group (warp-uniform)
    int x = blockIdx.x * 32 + tx;
    int y = blockIdx.y;
    int dblk = blockIdx.z;
    int d0 = dblk * DBLK_;
    int p = y * W_ + x;

    float v0[DBLK_], v1[DBLK_];

    if (g_fast) {
        float4 r = g_ref4[g * HW_ + p];
        int kb0 = g_kb[0][dblk];
        int kb1 = g_kb[1][dblk];
        int xlo = blockIdx.x * 32;
        bool interior = (xlo + kb0 >= 0) && (xlo + 31 + kb0 + 2 <= W_ - 1) &&
                        (xlo + kb1 >= 0) && (xlo + 31 + kb1 + 2 <= W_ - 1);
        if (interior) {
#pragma unroll
            for (int s = 0; s < S_; s++) {
                int kb = (s == 0) ? kb0 : kb1;
                const ulonglong2* sp =
                    (const ulonglong2*)(g_src4 + (s * G_ + g) * HW_ + y * W_) + x + kb;
                ulonglong2 q[3];
                q[0] = sp[0];
                q[1] = sp[1];
                q[2] = sp[2];
                depth_loop(q, s, d0, r, (s == 0) ? v0 : v1);
            }
        } else {
#pragma unroll
            for (int s = 0; s < S_; s++) {
                int kb = (s == 0) ? kb0 : kb1;
                const ulonglong2* sp =
                    (const ulonglong2*)(g_src4 + (s * G_ + g) * HW_ + y * W_);
                ulonglong2 q[3];
#pragma unroll
                for (int j = 0; j < 3; j++) {
                    int xc = x + kb + j;
                    bool valid = ((unsigned)xc < W_);
                    int xi = min(max(xc, 0), W_ - 1);
                    ulonglong2 qq = sp[xi];
                    q[j].x = valid ? qq.x : 0ull;
                    q[j].y = valid ? qq.y : 0ull;
                }
                depth_loop(q, s, d0, r, (s == 0) ? v0 : v1);
            }
        }
    } else {
        general_body(x, y, p, g, d0, depths, v0, v1);
    }

    // Stage per-group lin contributions; 8 reducer warps (dl = g) compute the
    // sigmoid weights once per (x, d); all threads then scale and store.
    float w1g = g_w1[g];
#pragma unroll
    for (int dl = 0; dl < DBLK_; dl++) {
        s_lin[dl][0][g][tx] = w1g * v0[dl];
        s_lin[dl][1][g][tx] = w1g * v1[dl];
    }
    __syncthreads();
    {
        int dl = g;  // DBLK_ == G_ == 8: every warp reduces one depth slot
        float L0 = 0.0f, L1 = 0.0f;
#pragma unroll
        for (int gg = 0; gg < G_; gg++) {
            L0 += s_lin[dl][0][gg][tx];
            L1 += s_lin[dl][1][gg][tx];
        }
        float s1 = g_aff[0], c1 = g_aff[1], w2c = g_aff[2], b2c = g_aff[3];
        float bn0 = fmaf(L0, s1, c1);
        float bn1 = fmaf(L1, s1, c1);
        float ac0 = fmaf(fmaxf(bn0, 0.0f), w2c, b2c);
        float ac1 = fmaf(fmaxf(bn1, 0.0f), w2c, b2c);
        float wgt0 = __fdividef(1.0f, 1.0f + __expf(-ac0));
        float wgt1 = __fdividef(1.0f, 1.0f + __expf(-ac1));
        float iw = __fdividef(1.0f, wgt0 + wgt1);
        s_w[dl][0][tx] = wgt0 * iw;
        s_w[dl][1][tx] = wgt1 * iw;
    }
    __syncthreads();

    float* op = out + (g * D_ + d0) * HW_ + p;
#pragma unroll
    for (int dl = 0; dl < DBLK_; dl++) {
        op[dl * HW_] = fmaf(s_w[dl][0][tx], v0[dl], s_w[dl][1][tx] * v1[dl]);
    }
}

// ---------------------------------------------------------------------------
// Launch
// ---------------------------------------------------------------------------
extern "C" void kernel_launch(void* const* d_in, const int* in_sizes, int n_in,
                              void* d_out, int out_size) {
    const float* ref_feature = (const float*)d_in[0];
    const float* src_features = (const float*)d_in[1];
    const float* ref_proj = (const float*)d_in[2];
    const float* src_projs = (const float*)d_in[3];
    const float* depth_hypos = (const float*)d_in[4];
    const float* w1 = (const float*)d_in[5];
    const float* bn_gamma = (const float*)d_in[6];
    const float* bn_beta = (const float*)d_in[7];
    const float* bn_mean = (const float*)d_in[8];
    const float* bn_var = (const float*)d_in[9];
    const float* w2 = (const float*)d_in[10];
    const float* b2 = (const float*)d_in[11];
    float* out = (float*)d_out;

    prep_all_kernel<<<(T2_ + 255) / 256, 256>>>(
        ref_feature, src_features, ref_proj, src_projs, depth_hypos, w1,
        bn_gamma, bn_beta, bn_mean, bn_var, w2, b2);

    dim3 grid(W_ / 32, H_, D_ / DBLK_);
    dim3 block(32, 8);
    fuse_kernel<<<grid, block>>>(depth_hypos, out);
}

// round 17
// speedup vs baseline: 1.0406x; 1.0406x over previous
#include <cuda_runtime.h>
#include <math.h>

// Problem shape (fixed by the dataset)
#define W_ 160
#define H_ 128
#define C_ 32
#define G_ 8
#define D_ 48
#define S_ 2
#define HW_ (H_ * W_)
#define DBLK_ 8
#define NDB_ (D_ / DBLK_)

#define SNAP_ 3e-5f
#define LOG2E_ 1.44269504088896340736f

typedef unsigned long long u64;

// Scratch (no cudaMalloc allowed)
__device__ float4 g_ref4[G_ * HW_];          // ref softmax, channel-packed
__device__ float4 g_src4[S_ * G_ * HW_];     // src features, channel-packed
__device__ float g_rot[S_][9];
__device__ float g_trans[S_][3];
__device__ float g_w1[G_];
__device__ float g_aff[4];  // s1, c1, w2, b2
// Fast-geometry tables (valid when g_fast != 0)
__device__ int    g_fast;
__device__ int    g_kb[S_][NDB_];
__device__ float4 g_w3[S_][D_];

__device__ __forceinline__ float ex2f(float x) {
    float y; asm("ex2.approx.f32 %0, %1;" : "=f"(y) : "f"(x)); return y;
}
__device__ __forceinline__ u64 pk2(float a, float b) {
    u64 r; asm("mov.b64 %0, {%1, %2};" : "=l"(r) : "f"(a), "f"(b)); return r;
}
__device__ __forceinline__ void upk2(u64 v, float& a, float& b) {
    asm("mov.b64 {%0, %1}, %2;" : "=f"(a), "=f"(b) : "l"(v));
}
__device__ __forceinline__ u64 fma2(u64 a, u64 b, u64 c) {
    u64 r; asm("fma.rn.f32x2 %0, %1, %2, %3;" : "=l"(r) : "l"(a), "l"(b), "l"(c)); return r;
}
__device__ __forceinline__ u64 mul2(u64 a, u64 b) {
    u64 r; asm("mul.rn.f32x2 %0, %1, %2;" : "=l"(r) : "l"(a), "l"(b)); return r;
}

// ---------------------------------------------------------------------------
// Prep (unchanged from R16)
// ---------------------------------------------------------------------------
#define T1_ (S_ * G_ * HW_)
#define T2_ (T1_ + G_ * HW_)

__global__ __launch_bounds__(256) void prep_all_kernel(
    const float* __restrict__ ref_feature,
    const float* __restrict__ srcF,
    const float* __restrict__ ref_proj,
    const float* __restrict__ src_projs,
    const float* __restrict__ depths,
    const float* __restrict__ w1,
    const float* __restrict__ bn_gamma,
    const float* __restrict__ bn_beta,
    const float* __restrict__ bn_mean,
    const float* __restrict__ bn_var,
    const float* __restrict__ w2,
    const float* __restrict__ b2) {
    int t = blockIdx.x * blockDim.x + threadIdx.x;

    if (blockIdx.x == 0) {
        if (threadIdx.x == 0) {
            float a[4][8];
            for (int i = 0; i < 4; i++)
                for (int j = 0; j < 4; j++) {
                    a[i][j] = ref_proj[i * 4 + j];
                    a[i][4 + j] = (i == j) ? 1.0f : 0.0f;
                }
            for (int col = 0; col < 4; col++) {
                int piv = col;
                float best = fabsf(a[col][col]);
                for (int r = col + 1; r < 4; r++) {
                    float v = fabsf(a[r][col]);
                    if (v > best) { best = v; piv = r; }
                }
                if (piv != col)
                    for (int j = 0; j < 8; j++) {
                        float tmp = a[col][j]; a[col][j] = a[piv][j]; a[piv][j] = tmp;
                    }
                float inv = 1.0f / a[col][col];
                for (int j = 0; j < 8; j++) a[col][j] *= inv;
                for (int r = 0; r < 4; r++) {
                    if (r == col) continue;
                    float f = a[r][col];
                    for (int j = 0; j < 8; j++) a[r][j] -= f * a[col][j];
                }
            }
            for (int s = 0; s < S_; s++) {
                const float* sp = src_projs + s * 16;
                for (int i = 0; i < 3; i++) {
                    float pr[4];
                    for (int j = 0; j < 4; j++) {
                        float acc = 0.0f;
                        for (int k = 0; k < 4; k++)
                            acc += sp[i * 4 + k] * a[k][4 + j];
                        pr[j] = acc;
                    }
                    g_rot[s][i * 3 + 0] = pr[0];
                    g_rot[s][i * 3 + 1] = pr[1];
                    g_rot[s][i * 3 + 2] = pr[2];
                    g_trans[s][i] = pr[3];
                }
            }
            for (int g = 0; g < G_; g++) g_w1[g] = w1[g];
            float s1 = bn_gamma[0] * rsqrtf(bn_var[0] + 1e-5f);
            float c1 = bn_beta[0] - bn_mean[0] * s1;
            g_aff[0] = s1;
            g_aff[1] = c1;
            g_aff[2] = w2[0];
            g_aff[3] = b2[0];

            bool fast = true;
            for (int s = 0; s < S_; s++) {
                for (int i = 0; i < 3; i++)
                    for (int j = 0; j < 3; j++) {
                        float expect = (i == j) ? 1.0f : 0.0f;
                        if (fabsf(g_rot[s][i * 3 + j] - expect) > 1e-3f) fast = false;
                    }
                if (fabsf(g_trans[s][1]) > 1e-3f) fast = false;
                if (fabsf(g_trans[s][2]) > 1e-3f) fast = false;
            }
            g_fast = fast ? 1 : 0;
        }
        __syncthreads();  // block-uniform
        if (threadIdx.x < S_ * D_) {
            int s = threadIdx.x / D_;
            int d = threadIdx.x % D_;
            int dblk = d / DBLK_;
            float t0 = g_trans[s][0];
            int kmin = 0x7fffffff, kd = 0;
            float wxd = 0.0f;
            for (int dl = 0; dl < DBLK_; dl++) {
                int dd = dblk * DBLK_ + dl;
                float shift = __fdividef(t0, depths[dd]);
                float fs = floorf(shift);
                float wx = shift - fs;
                if (wx < SNAP_) { wx = 0.0f; }
                else if (wx > 1.0f - SNAP_) { wx = 0.0f; fs += 1.0f; }
                int k = (int)fs;
                kmin = min(kmin, k);
                if (dd == d) { kd = k; wxd = wx; }
            }
            if ((d % DBLK_) == 0) g_kb[s][dblk] = kmin;
            int delta = kd - kmin;
            if (delta > 1) atomicExch(&g_fast, 0);  // fast tables invalid
            float wlo = (1.0f - wxd) * LOG2E_;
            float whi = wxd * LOG2E_;
            float4 w3 = make_float4(0.0f, 0.0f, 0.0f, 0.0f);
            if (delta == 0) { w3.x = wlo; w3.y = whi; }
            else            { w3.y = wlo; w3.z = whi; }
            g_w3[s][d] = w3;
        }
    }

    if (t < T1_) {
        int p = t % HW_;
        int sg = t / HW_;
        int s = sg / G_;
        int g = sg % G_;
        const float* b = srcF + (s * C_ + 4 * g) * HW_ + p;
        float4 v;
        v.x = b[0];
        v.y = b[HW_];
        v.z = b[2 * HW_];
        v.w = b[3 * HW_];
        g_src4[sg * HW_ + p] = v;
    } else if (t < T2_) {
        int u = t - T1_;
        int p = u % HW_;
        int g = u / HW_;
        const float* b = ref_feature + (g * 4) * HW_ + p;
        float e0 = __expf(b[0]);
        float e1 = __expf(b[HW_]);
        float e2 = __expf(b[2 * HW_]);
        float e3 = __expf(b[3 * HW_]);
        float is = __fdividef(1.0f, (e0 + e1) + (e2 + e3));
        float4 o;
        o.x = e0 * is;
        o.y = e1 * is;
        o.z = e2 * is;
        o.w = e3 * is;
        g_ref4[g * HW_ + p] = o;
    }
}

// Stride (in floats) between consecutive dl entries of s_v: [DBLK][2][G][32]
#define SV_STRIDE_ (2 * G_ * 32)

// ---------------------------------------------------------------------------
// General-geometry fallback, quarantined. Writes v straight into the smem
// result buffer (stride SV_STRIDE_ between depth slots).
// ---------------------------------------------------------------------------
__device__ __noinline__ void general_body(int x, int y, int p, int g, int d0,
                                          const float* __restrict__ depths,
                                          float* v0, float* v1) {
    const float4* sb0 = g_src4 + (0 * G_ + g) * HW_;
    const float4* sb1 = g_src4 + (1 * G_ + g) * HW_;
    float4 r = g_ref4[g * HW_ + p];
    float xf = (float)x, yf = (float)y;
    for (int dl = 0; dl < DBLK_; dl++) {
        float depth = __ldg(depths + d0 + dl);
        float vv[2];
        for (int s = 0; s < S_; s++) {
            float X = fmaf(fmaf(g_rot[s][0], xf, fmaf(g_rot[s][1], yf, g_rot[s][2])), depth, g_trans[s][0]);
            float Y = fmaf(fmaf(g_rot[s][3], xf, fmaf(g_rot[s][4], yf, g_rot[s][5])), depth, g_trans[s][1]);
            float Z = fmaf(fmaf(g_rot[s][6], xf, fmaf(g_rot[s][7], yf, g_rot[s][8])), depth, g_trans[s][2]);
            float iz = __fdividef(1.0f, Z);
            float px = X * iz;
            float py = Y * iz;
            float x0f = floorf(px), y0f = floorf(py);
            float wx = px - x0f, wy = py - y0f;
            if (wx < SNAP_) { wx = 0.0f; }
            else if (wx > 1.0f - SNAP_) { wx = 0.0f; x0f += 1.0f; }
            if (wy < SNAP_) { wy = 0.0f; }
            else if (wy > 1.0f - SNAP_) { wy = 0.0f; y0f += 1.0f; }
            float vx0 = (x0f >= 0.0f && x0f <= (float)(W_ - 1)) ? LOG2E_ : 0.0f;
            float vx1 = (x0f + 1.0f >= 0.0f && x0f + 1.0f <= (float)(W_ - 1)) ? LOG2E_ : 0.0f;
            float vy0 = (y0f >= 0.0f && y0f <= (float)(H_ - 1)) ? 1.0f : 0.0f;
            float vy1 = (y0f + 1.0f >= 0.0f && y0f + 1.0f <= (float)(H_ - 1)) ? 1.0f : 0.0f;
            float wl = (1.0f - wx) * vx0, wr = wx * vx1;
            float wt = (1.0f - wy) * vy0, wb = wy * vy1;
            int xi0 = min(max((int)x0f, 0), W_ - 1);
            int yi0 = min(max((int)y0f, 0), H_ - 1);
            int xi1 = min(max((int)x0f + 1, 0), W_ - 1);
            int yi1 = min(max((int)y0f + 1, 0), H_ - 1);
            const float4* sb = (s == 0) ? sb0 : sb1;
            float4 qa = sb[yi0 * W_ + xi0];
            float4 qb = sb[yi0 * W_ + xi1];
            float4 qc = sb[yi1 * W_ + xi0];
            float4 qd = sb[yi1 * W_ + xi1];
            float w00 = wl * wt, w01 = wr * wt, w10 = wl * wb, w11 = wr * wb;
            float a0 = fmaf(w00, qa.x, fmaf(w01, qb.x, fmaf(w10, qc.x, w11 * qd.x)));
            float a1 = fmaf(w00, qa.y, fmaf(w01, qb.y, fmaf(w10, qc.y, w11 * qd.y)));
            float a2 = fmaf(w00, qa.z, fmaf(w01, qb.z, fmaf(w10, qc.z, w11 * qd.z)));
            float a3 = fmaf(w00, qa.w, fmaf(w01, qb.w, fmaf(w10, qc.w, w11 * qd.w)));
            float e0 = ex2f(a0), e1 = ex2f(a1);
            float e2 = ex2f(a2), e3 = ex2f(a3);
            float ss = (e0 + e1) + (e2 + e3);
            float num = fmaf(e0, r.x, fmaf(e1, r.y, fmaf(e2, r.z, e3 * r.w)));
            vv[s] = __fdividef(num, ss);
        }
        v0[dl * SV_STRIDE_] = vv[0];
        v1[dl * SV_STRIDE_] = vv[1];
    }
}

// Depth loop over pre-loaded taps; results go straight to smem (strided).
__device__ __forceinline__ void depth_loop(const ulonglong2* q, int s, int d0,
                                           float4 r, float* vs) {
#pragma unroll
    for (int dl = 0; dl < DBLK_; dl++) {
        float4 w3 = g_w3[s][d0 + dl];
        u64 wa = pk2(w3.x, w3.x);
        u64 wb = pk2(w3.y, w3.y);
        u64 wc = pk2(w3.z, w3.z);
        u64 a01 = fma2(wa, q[0].x, fma2(wb, q[1].x, mul2(wc, q[2].x)));
        u64 a23 = fma2(wa, q[0].y, fma2(wb, q[1].y, mul2(wc, q[2].y)));
        float a0, a1, a2, a3;
        upk2(a01, a0, a1);
        upk2(a23, a2, a3);
        float e0 = ex2f(a0), e1 = ex2f(a1);
        float e2 = ex2f(a2), e3 = ex2f(a3);
        float ss = (e0 + e1) + (e2 + e3);
        float num = fmaf(e0, r.x, fmaf(e1, r.y, fmaf(e2, r.z, e3 * r.w)));
        vs[dl * SV_STRIDE_] = __fdividef(num, ss);
    }
}

// ---------------------------------------------------------------------------
// Main fused kernel. Grid (W/32, H, D/8); block (32, 8).
// v results live in SMEM, not registers: depth loop streams them out, the
// reduction reads them back with the w1 scale folded into its FMA, and the
// final combine re-reads them. Peak register live-range = one source's taps.
// ---------------------------------------------------------------------------
__global__ __launch_bounds__(256, 4) void fuse_kernel(const float* __restrict__ depths,
                                                      float* __restrict__ out) {
    __shared__ float s_v[DBLK_][2][G_][32];  // [dl][src][g][tx] = v value
    __shared__ float s_w[DBLK_][2][32];      // [dl][src][tx] = wgt*iw

    int tx = threadIdx.x;
    int g = threadIdx.y;                  // group (warp-uniform)
    int x = blockIdx.x * 32 + tx;
    int y = blockIdx.y;
    int dblk = blockIdx.z;
    int d0 = dblk * DBLK_;
    int p = y * W_ + x;

    float* sv0 = &s_v[0][0][g][tx];
    float* sv1 = &s_v[0][1][g][tx];

    if (g_fast) {
        float4 r = g_ref4[g * HW_ + p];
        int kb0 = g_kb[0][dblk];
        int kb1 = g_kb[1][dblk];
        int xlo = blockIdx.x * 32;
        bool interior = (xlo + kb0 >= 0) && (xlo + 31 + kb0 + 2 <= W_ - 1) &&
                        (xlo + kb1 >= 0) && (xlo + 31 + kb1 + 2 <= W_ - 1);
        if (interior) {
#pragma unroll
            for (int s = 0; s < S_; s++) {
                int kb = (s == 0) ? kb0 : kb1;
                const ulonglong2* sp =
                    (const ulonglong2*)(g_src4 + (s * G_ + g) * HW_ + y * W_) + x + kb;
                ulonglong2 q[3];
                q[0] = sp[0];
                q[1] = sp[1];
                q[2] = sp[2];
                depth_loop(q, s, d0, r, (s == 0) ? sv0 : sv1);
            }
        } else {
#pragma unroll
            for (int s = 0; s < S_; s++) {
                int kb = (s == 0) ? kb0 : kb1;
                const ulonglong2* sp =
                    (const ulonglong2*)(g_src4 + (s * G_ + g) * HW_ + y * W_);
                ulonglong2 q[3];
#pragma unroll
                for (int j = 0; j < 3; j++) {
                    int xc = x + kb + j;
                    bool valid = ((unsigned)xc < W_);
                    int xi = min(max(xc, 0), W_ - 1);
                    ulonglong2 qq = sp[xi];
                    q[j].x = valid ? qq.x : 0ull;
                    q[j].y = valid ? qq.y : 0ull;
                }
                depth_loop(q, s, d0, r, (s == 0) ? sv0 : sv1);
            }
        }
    } else {
        general_body(x, y, p, g, d0, depths, sv0, sv1);
    }

    __syncthreads();
    // Each warp reduces one depth slot (DBLK_ == G_ == 8): w1 scale folded
    // into the reduction FMA.
    {
        int dl = g;
        float L0 = 0.0f, L1 = 0.0f;
#pragma unroll
        for (int gg = 0; gg < G_; gg++) {
            float w1g = g_w1[gg];
            L0 = fmaf(w1g, s_v[dl][0][gg][tx], L0);
            L1 = fmaf(w1g, s_v[dl][1][gg][tx], L1);
        }
        float s1 = g_aff[0], c1 = g_aff[1], w2c = g_aff[2], b2c = g_aff[3];
        float bn0 = fmaf(L0, s1, c1);
        float bn1 = fmaf(L1, s1, c1);
        float ac0 = fmaf(fmaxf(bn0, 0.0f), w2c, b2c);
        float ac1 = fmaf(fmaxf(bn1, 0.0f), w2c, b2c);
        float wgt0 = __fdividef(1.0f, 1.0f + __expf(-ac0));
        float wgt1 = __fdividef(1.0f, 1.0f + __expf(-ac1));
        float iw = __fdividef(1.0f, wgt0 + wgt1);
        s_w[dl][0][tx] = wgt0 * iw;
        s_w[dl][1][tx] = wgt1 * iw;
    }
    __syncthreads();

    float* op = out + (g * D_ + d0) * HW_ + p;
#pragma unroll
    for (int dl = 0; dl < DBLK_; dl++) {
        op[dl * HW_] = fmaf(s_w[dl][0][tx], s_v[dl][0][g][tx],
                            s_w[dl][1][tx] * s_v[dl][1][g][tx]);
    }
}

// ---------------------------------------------------------------------------
// Launch
// ---------------------------------------------------------------------------
extern "C" void kernel_launch(void* const* d_in, const int* in_sizes, int n_in,
                              void* d_out, int out_size) {
    const float* ref_feature = (const float*)d_in[0];
    const float* src_features = (const float*)d_in[1];
    const float* ref_proj = (const float*)d_in[2];
    const float* src_projs = (const float*)d_in[3];
    const float* depth_hypos = (const float*)d_in[4];
    const float* w1 = (const float*)d_in[5];
    const float* bn_gamma = (const float*)d_in[6];
    const float* bn_beta = (const float*)d_in[7];
    const float* bn_mean = (const float*)d_in[8];
    const float* bn_var = (const float*)d_in[9];
    const float* w2 = (const float*)d_in[10];
    const float* b2 = (const float*)d_in[11];
    float* out = (float*)d_out;

    prep_all_kernel<<<(T2_ + 255) / 256, 256>>>(
        ref_feature, src_features, ref_proj, src_projs, depth_hypos, w1,
        bn_gamma, bn_beta, bn_mean, bn_var, w2, b2);

    dim3 grid(W_ / 32, H_, D_ / DBLK_);
    dim3 block(32, 8);
    fuse_kernel<<<grid, block>>>(depth_hypos, out);
}